// round 15
// baseline (speedup 1.0000x reference)
#include <cuda_runtime.h>
#include <cuda_bf16.h>
#include <cstdint>
#include <math.h>

// Problem constants
#define U_N   100000
#define B_N   50000
#define NN    150000
#define NA    200000
#define E_UB  800000
#define E_BB  600000
#define P_N   400000
#define DU    64
#define DB    128
#define H     128

// weight k-offsets in transposed hi/lo store
#define WO_WU   0
#define WO_WUB  64
#define WO_WBB  192
#define WO_WL1  320
#define WO_WR1  448
#define WO_WL2  576
#define WO_WR2  704
#define WO_WF1A 832
#define WO_WF1B 960
#define WT_TOTK 1088

// ---------------- device scratch ----------------
__device__ int   g_degall[NA];
__device__ int   g_offall[NA];
__device__ int   g_cur[NN];
__device__ int   g_curb[B_N];
__device__ int   g_adj[2 * E_UB];
__device__ int   g_adjb[E_BB];
__device__ int   g_bsums[1024];
__device__ float g_dinv[NN];
__device__ float g_acc[(size_t)NN * H];
__device__ float g_ya[(size_t)NN * H];
__device__ float g_yb[(size_t)NN * H];
__device__ float g_ha[(size_t)B_N * H];
__device__ float g_hb[(size_t)B_N * H];
__device__ float g_agg[(size_t)B_N * H];
__device__ float g_fused[(size_t)B_N * H];
__device__ uint32_t g_wt_hi[WT_TOTK * 64];   // [seg][n][k/2] bf16x2 pairs, W^T layout
__device__ uint32_t g_wt_lo[WT_TOTK * 64];

__device__ __forceinline__ float ftrunc16(float x) {
    return __uint_as_float(__float_as_uint(x) & 0xFFFF0000u);
}
__device__ __forceinline__ uint32_t bf16x2_pack(float lo_elem, float hi_elem) {
    uint32_t r;
    asm("cvt.rn.bf16x2.f32 %0, %1, %2;" : "=r"(r) : "f"(hi_elem), "f"(lo_elem));
    return r;
}

// ---------------- init: zero counters + precompute weight hi/lo panels ----------------
__global__ void k_init(const float* __restrict__ Wu, const float* __restrict__ Wub,
                       const float* __restrict__ Wbb, const float* __restrict__ Wl1,
                       const float* __restrict__ Wr1, const float* __restrict__ Wl2,
                       const float* __restrict__ Wr2, const float* __restrict__ Wf1) {
    int i = blockIdx.x * blockDim.x + threadIdx.x;
    if (i < NA) g_degall[i] = 0;
    if (i < NN) g_cur[i] = 0;
    if (i < B_N) g_curb[i] = 0;
    if (i < WT_TOTK * 64) {
        const int offs[10] = {0, 64, 192, 320, 448, 576, 704, 832, 960, 1088};
        const float* Wp[9] = {Wu, Wub, Wbb, Wl1, Wr1, Wl2, Wr2, Wf1, Wf1 + 128 * 128};
        int e = i * 2;
        int s = 0;
        while (e >= offs[s + 1] * 128) s++;
        int Kw = offs[s + 1] - offs[s];
        int loc = e - offs[s] * 128;
        int n = loc / Kw, k = loc - n * Kw;
        const float* W = Wp[s];
        float a = W[(size_t)k * H + n];
        float b = W[(size_t)(k + 1) * H + n];
        g_wt_hi[i] = __byte_perm(__float_as_uint(a), __float_as_uint(b), 0x7632);
        g_wt_lo[i] = bf16x2_pack(a - ftrunc16(a), b - ftrunc16(b));
    }
}

// ---------------- graph build ----------------
__global__ void k_deg(const int* __restrict__ usrc, const int* __restrict__ udst,
                      const int* __restrict__ bdst) {
    int e = blockIdx.x * blockDim.x + threadIdx.x;
    if (e < E_UB) {
        atomicAdd(&g_degall[usrc[e]], 1);
        atomicAdd(&g_degall[U_N + udst[e]], 1);
    }
    if (e < E_BB) atomicAdd(&g_degall[NN + bdst[e]], 1);
}

__global__ void k_blocksum(const int* __restrict__ in, int n, int* __restrict__ bs) {
    __shared__ int sh[1024];
    int t = threadIdx.x, i = blockIdx.x * 1024 + t;
    sh[t] = (i < n) ? in[i] : 0;
    __syncthreads();
    for (int s = 512; s > 0; s >>= 1) {
        if (t < s) sh[t] += sh[t + s];
        __syncthreads();
    }
    if (t == 0) bs[blockIdx.x] = sh[0];
}

__global__ void k_scan_small(int* bs, int nb) {
    __shared__ int sh[1024];
    int t = threadIdx.x;
    sh[t] = (t < nb) ? bs[t] : 0;
    __syncthreads();
    for (int o = 1; o < 1024; o <<= 1) {
        int v = (t >= o) ? sh[t - o] : 0;
        __syncthreads();
        sh[t] += v;
        __syncthreads();
    }
    if (t < nb) bs[t] = t ? sh[t - 1] : 0;
}

__global__ void k_scan_block(const int* __restrict__ in, int n,
                             const int* __restrict__ bs, int* __restrict__ out) {
    __shared__ int sh[1024];
    int t = threadIdx.x, i = blockIdx.x * 1024 + t;
    int d = (i < n) ? in[i] : 0;
    sh[t] = d;
    __syncthreads();
    for (int o = 1; o < 1024; o <<= 1) {
        int v = (t >= o) ? sh[t - o] : 0;
        __syncthreads();
        sh[t] += v;
        __syncthreads();
    }
    if (i < n) {
        out[i] = (t ? sh[t - 1] : 0) + bs[blockIdx.x];
        if (i < NN) g_dinv[i] = (d > 0) ? rsqrtf((float)d) : 0.0f;
    }
}

// ---------------- bf16 split-3 HMMA GEMM core ----------------
#define GF_RELU   2
#define GF_WRITEY 4
#define GF_FUSE   16

#define MMA_BF16(d, a, b) \
    asm volatile("mma.sync.aligned.m16n8k16.row.col.f32.bf16.bf16.f32 " \
                 "{%0,%1,%2,%3}, {%4,%5,%6,%7}, {%8,%9}, {%0,%1,%2,%3};" \
                 : "+f"((d)[0]), "+f"((d)[1]), "+f"((d)[2]), "+f"((d)[3]) \
                 : "r"((a)[0]), "r"((a)[1]), "r"((a)[2]), "r"((a)[3]), \
                   "r"((b)[0]), "r"((b)[1]))

struct SmemT {
    __nv_bfloat16 Ah[128][36];
    __nv_bfloat16 Al[128][36];
    __nv_bfloat16 Bh[128][34];
    __nv_bfloat16 Bl[128][34];
    float z0s[4][128];
    float z1s[4][128];
};

__device__ __forceinline__ void gemm_body(
    SmemT& sm, int mblk,
    const float* __restrict__ A1, int wo1, int K1, float s1,
    const float* __restrict__ A2, int wo2, int K2,
    const float* __restrict__ bias, float* __restrict__ C, int M, int flags,
    float* __restrict__ Y, const float* __restrict__ dinv,
    const float* __restrict__ Wf2, const float* __restrict__ bf2) {
    const int tid = threadIdx.x;
    const int lane = tid & 31, wid = tid >> 5;
    const int g = lane >> 2, t = lane & 3;
    const int wm = wid >> 2, wn = wid & 3;
    const int m0 = mblk * 128;
    const int np1 = K1 >> 5, np = np1 + (K2 >> 5);

    float acc[4][4][4];
#pragma unroll
    for (int i = 0; i < 4; i++)
#pragma unroll
        for (int j = 0; j < 4; j++) {
            acc[i][j][0] = 0.f; acc[i][j][1] = 0.f;
            acc[i][j][2] = 0.f; acc[i][j][3] = 0.f;
        }

    int arow[4], ac4[4];
#pragma unroll
    for (int i = 0; i < 4; i++) {
        int idx = tid + (i << 8);
        arow[i] = idx >> 3;
        ac4[i] = (idx & 7) << 2;
    }
    const int bn0 = (tid * 2) >> 2, bg0 = (tid * 2) & 3;
    const int bn1 = (tid * 2 + 1) >> 2, bg1 = (tid * 2 + 1) & 3;

    float4 av[4];
    float scs;
    {
        const float* Ap = np1 ? A1 : A2;
        int Ks = np1 ? K1 : K2;
        scs = np1 ? s1 : 1.0f;
#pragma unroll
        for (int i = 0; i < 4; i++) {
            int m = m0 + arow[i];
            av[i] = make_float4(0.f, 0.f, 0.f, 0.f);
            if (m < M) av[i] = *(const float4*)(Ap + (size_t)m * Ks + ac4[i]);
        }
    }

    for (int p = 0; p < np; p++) {
        int wo, Kw, kl;
        if (p < np1) { wo = wo1; Kw = K1; kl = p << 5; }
        else         { wo = wo2; Kw = K2; kl = (p - np1) << 5; }

        const uint32_t* bhp = g_wt_hi + wo * 64;
        const uint32_t* blp = g_wt_lo + wo * 64;
        int bi0 = ((bn0 * Kw + kl) >> 1) + bg0 * 4;
        int bi1 = ((bn1 * Kw + kl) >> 1) + bg1 * 4;
        uint4 BH0 = *(const uint4*)(bhp + bi0);
        uint4 BH1 = *(const uint4*)(bhp + bi1);
        uint4 BL0 = *(const uint4*)(blp + bi0);
        uint4 BL1 = *(const uint4*)(blp + bi1);

#pragma unroll
        for (int i = 0; i < 4; i++) {
            float x0 = scs * av[i].x, x1 = scs * av[i].y;
            float x2 = scs * av[i].z, x3 = scs * av[i].w;
            uint32_t hp0 = __byte_perm(__float_as_uint(x0), __float_as_uint(x1), 0x7632);
            uint32_t hp1 = __byte_perm(__float_as_uint(x2), __float_as_uint(x3), 0x7632);
            uint32_t lp0 = bf16x2_pack(x0 - ftrunc16(x0), x1 - ftrunc16(x1));
            uint32_t lp1 = bf16x2_pack(x2 - ftrunc16(x2), x3 - ftrunc16(x3));
            *(uint32_t*)&sm.Ah[arow[i]][ac4[i]]     = hp0;
            *(uint32_t*)&sm.Ah[arow[i]][ac4[i] + 2] = hp1;
            *(uint32_t*)&sm.Al[arow[i]][ac4[i]]     = lp0;
            *(uint32_t*)&sm.Al[arow[i]][ac4[i] + 2] = lp1;
        }
        *(uint32_t*)&sm.Bh[bn0][bg0 * 8 + 0] = BH0.x;
        *(uint32_t*)&sm.Bh[bn0][bg0 * 8 + 2] = BH0.y;
        *(uint32_t*)&sm.Bh[bn0][bg0 * 8 + 4] = BH0.z;
        *(uint32_t*)&sm.Bh[bn0][bg0 * 8 + 6] = BH0.w;
        *(uint32_t*)&sm.Bh[bn1][bg1 * 8 + 0] = BH1.x;
        *(uint32_t*)&sm.Bh[bn1][bg1 * 8 + 2] = BH1.y;
        *(uint32_t*)&sm.Bh[bn1][bg1 * 8 + 4] = BH1.z;
        *(uint32_t*)&sm.Bh[bn1][bg1 * 8 + 6] = BH1.w;
        *(uint32_t*)&sm.Bl[bn0][bg0 * 8 + 0] = BL0.x;
        *(uint32_t*)&sm.Bl[bn0][bg0 * 8 + 2] = BL0.y;
        *(uint32_t*)&sm.Bl[bn0][bg0 * 8 + 4] = BL0.z;
        *(uint32_t*)&sm.Bl[bn0][bg0 * 8 + 6] = BL0.w;
        *(uint32_t*)&sm.Bl[bn1][bg1 * 8 + 0] = BL1.x;
        *(uint32_t*)&sm.Bl[bn1][bg1 * 8 + 2] = BL1.y;
        *(uint32_t*)&sm.Bl[bn1][bg1 * 8 + 4] = BL1.z;
        *(uint32_t*)&sm.Bl[bn1][bg1 * 8 + 6] = BL1.w;
        __syncthreads();

        float nsc = scs;
        if (p + 1 < np) {
            int q = p + 1;
            const float* Ap; int Ks, kl2;
            if (q < np1) { Ap = A1; Ks = K1; kl2 = q << 5; nsc = s1; }
            else         { Ap = A2; Ks = K2; kl2 = (q - np1) << 5; nsc = 1.0f; }
#pragma unroll
            for (int i = 0; i < 4; i++) {
                int m = m0 + arow[i];
                av[i] = make_float4(0.f, 0.f, 0.f, 0.f);
                if (m < M) av[i] = *(const float4*)(Ap + (size_t)m * Ks + kl2 + ac4[i]);
            }
        }

#pragma unroll
        for (int ks = 0; ks < 2; ks++) {
            const int kk = (ks << 4) + 2 * t;
            uint32_t bh[4][2], bl[4][2];
#pragma unroll
            for (int nf = 0; nf < 4; nf++) {
                int n = (wn << 5) + (nf << 3) + g;
                bh[nf][0] = *(const uint32_t*)&sm.Bh[n][kk];
                bh[nf][1] = *(const uint32_t*)&sm.Bh[n][kk + 8];
                bl[nf][0] = *(const uint32_t*)&sm.Bl[n][kk];
                bl[nf][1] = *(const uint32_t*)&sm.Bl[n][kk + 8];
            }
#pragma unroll
            for (int mf = 0; mf < 4; mf++) {
                int r = (wm << 6) + (mf << 4) + g;
                uint32_t ah[4], al[4];
                ah[0] = *(const uint32_t*)&sm.Ah[r][kk];
                ah[1] = *(const uint32_t*)&sm.Ah[r + 8][kk];
                ah[2] = *(const uint32_t*)&sm.Ah[r][kk + 8];
                ah[3] = *(const uint32_t*)&sm.Ah[r + 8][kk + 8];
                al[0] = *(const uint32_t*)&sm.Al[r][kk];
                al[1] = *(const uint32_t*)&sm.Al[r + 8][kk];
                al[2] = *(const uint32_t*)&sm.Al[r][kk + 8];
                al[3] = *(const uint32_t*)&sm.Al[r + 8][kk + 8];
#pragma unroll
                for (int nf = 0; nf < 4; nf++) {
                    MMA_BF16(acc[mf][nf], ah, bh[nf]);
                    MMA_BF16(acc[mf][nf], ah, bl[nf]);
                    MMA_BF16(acc[mf][nf], al, bh[nf]);
                }
            }
        }
        __syncthreads();
        scs = nsc;
    }

    if (!(flags & GF_FUSE)) {
#pragma unroll
        for (int mf = 0; mf < 4; mf++) {
#pragma unroll
            for (int half = 0; half < 2; half++) {
                int r = m0 + (wm << 6) + (mf << 4) + g + half * 8;
                if (r >= M) continue;
                float dv = (flags & GF_WRITEY) ? dinv[r] : 0.f;
#pragma unroll
                for (int nf = 0; nf < 4; nf++) {
                    int c = (wn << 5) + (nf << 3) + 2 * t;
                    float v0 = acc[mf][nf][half * 2 + 0];
                    float v1 = acc[mf][nf][half * 2 + 1];
                    if (bias) { v0 += __ldg(bias + c); v1 += __ldg(bias + c + 1); }
                    if (flags & GF_RELU) { v0 = fmaxf(v0, 0.f); v1 = fmaxf(v1, 0.f); }
                    *(float2*)(C + (size_t)r * H + c) = make_float2(v0, v1);
                    if (flags & GF_WRITEY)
                        *(float2*)(Y + (size_t)r * H + c) = make_float2(dv * v0, dv * v1);
                }
            }
        }
    } else {
        // fused attention epilogue
#pragma unroll
        for (int mf = 0; mf < 4; mf++) {
#pragma unroll
            for (int half = 0; half < 2; half++) {
                float z0 = 0.f, z1 = 0.f;
#pragma unroll
                for (int nf = 0; nf < 4; nf++) {
                    int c = (wn << 5) + (nf << 3) + 2 * t;
                    float v0 = fmaxf(acc[mf][nf][half * 2 + 0] + __ldg(bias + c), 0.f);
                    float v1 = fmaxf(acc[mf][nf][half * 2 + 1] + __ldg(bias + c + 1), 0.f);
                    const float* w2 = Wf2 + 2 * c;
                    z0 += v0 * __ldg(w2 + 0) + v1 * __ldg(w2 + 2);
                    z1 += v0 * __ldg(w2 + 1) + v1 * __ldg(w2 + 3);
                }
                z0 += __shfl_xor_sync(0xffffffffu, z0, 1);
                z0 += __shfl_xor_sync(0xffffffffu, z0, 2);
                z1 += __shfl_xor_sync(0xffffffffu, z1, 1);
                z1 += __shfl_xor_sync(0xffffffffu, z1, 2);
                if (t == 0) {
                    int rl = (wm << 6) + (mf << 4) + g + half * 8;
                    sm.z0s[wn][rl] = z0;
                    sm.z1s[wn][rl] = z1;
                }
            }
        }
        __syncthreads();
        const float third = 1.0f / 3.0f;
        float b0 = __ldg(bf2), b1 = __ldg(bf2 + 1);
#pragma unroll
        for (int mf = 0; mf < 4; mf++) {
#pragma unroll
            for (int half = 0; half < 2; half++) {
                int rl = (wm << 6) + (mf << 4) + g + half * 8;
                int r = m0 + rl;
                if (r >= M) continue;
                float z0 = sm.z0s[0][rl] + sm.z0s[1][rl] + sm.z0s[2][rl] + sm.z0s[3][rl] + b0;
                float z1 = sm.z1s[0][rl] + sm.z1s[1][rl] + sm.z1s[2][rl] + sm.z1s[3][rl] + b1;
                float mx = fmaxf(z0, z1);
                float e0 = expf(z0 - mx), e1 = expf(z1 - mx);
                float inv = 1.0f / (e0 + e1);
                float a0 = e0 * inv * third, a1 = e1 * inv;
#pragma unroll
                for (int nf = 0; nf < 4; nf++) {
                    int c = (wn << 5) + (nf << 3) + 2 * t;
                    float2 cb = *(const float2*)(g_acc + (size_t)(U_N + r) * H + c);
                    float2 ct = *(const float2*)(g_ha + (size_t)r * H + c);
                    *(float2*)(g_fused + (size_t)r * H + c) =
                        make_float2(a0 * cb.x + a1 * ct.x, a0 * cb.y + a1 * ct.y);
                }
            }
        }
    }
}

#define GU_BLKS 782
#define GB_BLKS 391
#define GEMM3_BLKS (GU_BLKS + 2 * GB_BLKS)    // 1564
#define FILL_BLKS ((E_UB + 255) / 256)        // 3125

// merged: projections (blocks [0,GEMM3)) + adjacency fill (rest)
__global__ __launch_bounds__(256)
void k_fillgemm(const int* __restrict__ usrc, const int* __restrict__ udst,
                const int* __restrict__ bsrc, const int* __restrict__ bdst,
                const float* __restrict__ user_x, const float* __restrict__ book_x,
                const float* __restrict__ bu, const float* __restrict__ bub,
                const float* __restrict__ bbb) {
    __shared__ SmemT sm;
    int b = blockIdx.x;
    if (b < GEMM3_BLKS) {
        const float* A; const float* bi; float* Cp; float* Yp; const float* dv;
        int wo, K, M, fl, mblk;
        if (b < GU_BLKS) {
            mblk = b; A = user_x; wo = WO_WU; K = DU; M = U_N; bi = bu;
            Cp = g_acc; fl = GF_WRITEY; Yp = g_ya; dv = g_dinv;
        } else if (b < GU_BLKS + GB_BLKS) {
            mblk = b - GU_BLKS; A = book_x; wo = WO_WUB; K = DB; M = B_N; bi = bub;
            Cp = g_acc + (size_t)U_N * H; fl = GF_WRITEY;
            Yp = g_ya + (size_t)U_N * H; dv = g_dinv + U_N;
        } else {
            mblk = b - GU_BLKS - GB_BLKS; A = book_x; wo = WO_WBB; K = DB; M = B_N;
            bi = bbb; Cp = g_ha; fl = 0; Yp = nullptr; dv = nullptr;
        }
        gemm_body(sm, mblk, A, wo, K, 1.0f, nullptr, 0, 0, bi, Cp, M, fl, Yp, dv,
                  nullptr, nullptr);
    } else {
        int e = (b - GEMM3_BLKS) * 256 + threadIdx.x;
        if (e < E_UB) {
            int u = usrc[e], bb = U_N + udst[e];
            int p = atomicAdd(&g_cur[u], 1);
            g_adj[g_offall[u] + p] = bb;
            int q = atomicAdd(&g_cur[bb], 1);
            g_adj[g_offall[bb] + q] = u;
        }
        if (e < E_BB) {
            int d = bdst[e];
            int p = atomicAdd(&g_curb[d], 1);
            g_adjb[g_offall[NN + d] - 2 * E_UB + p] = bsrc[e];
        }
    }
}

__global__ __launch_bounds__(256)
void k_gemm1(const float* __restrict__ A1, int wo1, int K1, float s1,
             const float* __restrict__ A2, int wo2, int K2,
             const float* __restrict__ bias, float* __restrict__ C,
             int M, int flags,
             const float* __restrict__ Wf2, const float* __restrict__ bf2) {
    __shared__ SmemT sm;
    gemm_body(sm, blockIdx.x, A1, wo1, K1, s1, A2, wo2, K2, bias, C, M, flags,
              nullptr, nullptr, Wf2, bf2);
}

// ---- merged SpMV: LightGCN (warps [0,NN)) + SAGE mean-agg (warps [NN,NN+B_N)) ----
__global__ void k_spmv(const float4* __restrict__ yin, float4* __restrict__ yout,
                       int write_yn, const float4* __restrict__ hin) {
    int w = (blockIdx.x * blockDim.x + threadIdx.x) >> 5;
    int lane = threadIdx.x & 31;
    if (w < NN) {
        int start = g_offall[w], d = g_degall[w];
        float4 s = make_float4(0.f, 0.f, 0.f, 0.f);
        int base = 0;
        for (; base + 32 <= d; base += 32) {
            int nb = g_adj[start + base + lane];
#pragma unroll
            for (int j = 0; j < 32; j++) {
                int nbj = __shfl_sync(0xffffffffu, nb, j);
                float4 v = yin[(size_t)nbj * 32 + lane];
                s.x += v.x; s.y += v.y; s.z += v.z; s.w += v.w;
            }
        }
        int rem = d - base;
        if (rem) {
            int nb = (lane < rem) ? g_adj[start + base + lane] : 0;
#pragma unroll 4
            for (int j = 0; j < rem; j++) {
                int nbj = __shfl_sync(0xffffffffu, nb, j);
                float4 v = yin[(size_t)nbj * 32 + lane];
                s.x += v.x; s.y += v.y; s.z += v.z; s.w += v.w;
            }
        }
        float di = g_dinv[w];
        size_t o = (size_t)w * 32 + lane;
        float4 aa = ((float4*)g_acc)[o];
        aa.x += di * s.x; aa.y += di * s.y; aa.z += di * s.z; aa.w += di * s.w;
        ((float4*)g_acc)[o] = aa;
        if (write_yn) {
            float dd = di * di;
            yout[o] = make_float4(dd * s.x, dd * s.y, dd * s.z, dd * s.w);
        }
    } else if (w < NN + B_N) {
        int wb = w - NN;
        int start = g_offall[NN + wb] - 2 * E_UB, d = g_degall[NN + wb];
        float4 s = make_float4(0.f, 0.f, 0.f, 0.f);
        int base = 0;
        for (; base + 32 <= d; base += 32) {
            int nb = g_adjb[start + base + lane];
#pragma unroll
            for (int j = 0; j < 32; j++) {
                int nbj = __shfl_sync(0xffffffffu, nb, j);
                float4 v = hin[(size_t)nbj * 32 + lane];
                s.x += v.x; s.y += v.y; s.z += v.z; s.w += v.w;
            }
        }
        int rem = d - base;
        if (rem) {
            int nb = (lane < rem) ? g_adjb[start + base + lane] : 0;
#pragma unroll 4
            for (int j = 0; j < rem; j++) {
                int nbj = __shfl_sync(0xffffffffu, nb, j);
                float4 v = hin[(size_t)nbj * 32 + lane];
                s.x += v.x; s.y += v.y; s.z += v.z; s.w += v.w;
            }
        }
        float inv = 1.0f / (float)max(d, 1);
        ((float4*)g_agg)[(size_t)wb * 32 + lane] =
            make_float4(inv * s.x, inv * s.y, inv * s.z, inv * s.w);
    }
}

// ---------------- final scoring: quarter-warp (8 lanes) per pair ----------------
__global__ void k_score(const int* __restrict__ pu, const int* __restrict__ pb,
                        float* __restrict__ out) {
    int q = (blockIdx.x * blockDim.x + threadIdx.x) >> 3;
    int l8 = threadIdx.x & 7;
    if (q >= P_N) return;
    int u = pu[q], b = pb[q];
    const float4* ar = (const float4*)g_acc + (size_t)u * 32;
    const float4* fr = (const float4*)g_fused + (size_t)b * 32;
    float s = 0.f;
#pragma unroll
    for (int c = 0; c < 4; c++) {
        float4 a = ar[l8 + c * 8];
        float4 f = fr[l8 + c * 8];
        s += a.x * f.x + a.y * f.y + a.z * f.z + a.w * f.w;
    }
#pragma unroll
    for (int o = 4; o > 0; o >>= 1) s += __shfl_xor_sync(0xffffffffu, s, o);
    if (l8 == 0) out[q] = s * (1.0f / 3.0f);
}

// ---------------- host ----------------
extern "C" void kernel_launch(void* const* d_in, const int* in_sizes, int n_in,
                              void* d_out, int out_size) {
    const float* user_x = (const float*)d_in[0];
    const float* book_x = (const float*)d_in[1];
    const int* ub_src = (const int*)d_in[2];
    const int* ub_dst = (const int*)d_in[3];
    const int* bb_src = (const int*)d_in[4];
    const int* bb_dst = (const int*)d_in[5];
    const int* pred_u = (const int*)d_in[6];
    const int* pred_b = (const int*)d_in[7];
    const float* Wu  = (const float*)d_in[8];
    const float* bu  = (const float*)d_in[9];
    const float* Wub = (const float*)d_in[10];
    const float* bub = (const float*)d_in[11];
    const float* Wbb = (const float*)d_in[12];
    const float* bbb = (const float*)d_in[13];
    const float* Wl1 = (const float*)d_in[14];
    const float* bl1 = (const float*)d_in[15];
    const float* Wr1 = (const float*)d_in[16];
    const float* Wl2 = (const float*)d_in[17];
    const float* bl2 = (const float*)d_in[18];
    const float* Wr2 = (const float*)d_in[19];
    const float* Wf1 = (const float*)d_in[20];
    const float* bf1 = (const float*)d_in[21];
    const float* Wf2 = (const float*)d_in[22];
    const float* bf2 = (const float*)d_in[23];
    float* out = (float*)d_out;

    void *p_acc, *p_ha, *p_hb, *p_agg, *p_deg, *p_off, *p_bs, *p_ya, *p_yb;
    cudaGetSymbolAddress(&p_acc, g_acc);
    cudaGetSymbolAddress(&p_ha, g_ha);
    cudaGetSymbolAddress(&p_hb, g_hb);
    cudaGetSymbolAddress(&p_agg, g_agg);
    cudaGetSymbolAddress(&p_deg, g_degall);
    cudaGetSymbolAddress(&p_off, g_offall);
    cudaGetSymbolAddress(&p_bs, g_bsums);
    cudaGetSymbolAddress(&p_ya, g_ya);
    cudaGetSymbolAddress(&p_yb, g_yb);
    float* acc = (float*)p_acc;
    float* ha = (float*)p_ha;
    float* hb = (float*)p_hb;
    float* agg = (float*)p_agg;
    int* dg = (int*)p_deg;
    int* off = (int*)p_off;
    int* bs = (int*)p_bs;
    float4* ya4 = (float4*)p_ya;
    float4* yb4 = (float4*)p_yb;
    float4* ha4 = (float4*)p_ha;
    float4* hb4 = (float4*)p_hb;

    const int TB = 256;
    const int NB_A = (NA + TB - 1) / TB;
    const int NB_E = (E_UB + TB - 1) / TB;
    const int SCAN_A = (NA + 1023) / 1024;
    const int SPMV_BLKS = ((NN + B_N) * 32 + TB - 1) / TB;

    // init + build prefix
    k_init<<<NB_A, TB>>>(Wu, Wub, Wbb, Wl1, Wr1, Wl2, Wr2, Wf1);
    k_deg<<<NB_E, TB>>>(ub_src, ub_dst, bb_dst);
    k_blocksum<<<SCAN_A, 1024>>>(dg, NA, bs);
    k_scan_small<<<1, 1024>>>(bs, SCAN_A);
    k_scan_block<<<SCAN_A, 1024>>>(dg, NA, bs, off);

    // merged: big projection GEMM + adjacency fill (independent work)
    k_fillgemm<<<GEMM3_BLKS + FILL_BLKS, 256>>>(ub_src, ub_dst, bb_src, bb_dst,
                                                user_x, book_x, bu, bub, bbb);

    // level 0: LightGCN hop1 + SAGE agg(ha)
    k_spmv<<<SPMV_BLKS, TB>>>(ya4, yb4, 1, ha4);

    // SAGE layer 1 (merged L+R)
    k_gemm1<<<GB_BLKS, 256>>>(agg, WO_WL1, H, 1.0f, ha, WO_WR1, H,
                              bl1, hb, B_N, GF_RELU, nullptr, nullptr);

    // level 1: LightGCN hop2 (no yn) + SAGE agg(hb)
    k_spmv<<<SPMV_BLKS, TB>>>(yb4, ya4, 0, hb4);

    // SAGE layer 2
    k_gemm1<<<GB_BLKS, 256>>>(agg, WO_WL2, H, 1.0f, hb, WO_WR2, H,
                              bl2, ha, B_N, GF_RELU, nullptr, nullptr);

    // fusion GEMM with fused attention epilogue
    k_gemm1<<<GB_BLKS, 256>>>(acc + (size_t)U_N * H, WO_WF1A, H, 1.0f / 3.0f,
                              ha, WO_WF1B, H, bf1, nullptr, B_N, GF_FUSE,
                              Wf2, bf2);

    // scoring (quarter-warp per pair)
    k_score<<<(P_N * 8 + TB - 1) / TB, TB>>>(pred_u, pred_b, out);
}

// round 16
// speedup vs baseline: 1.0271x; 1.0271x over previous
#include <cuda_runtime.h>
#include <cuda_bf16.h>
#include <cstdint>
#include <math.h>

// Problem constants
#define U_N   100000
#define B_N   50000
#define NN    150000
#define NA    200000
#define E_UB  800000
#define E_BB  600000
#define P_N   400000
#define DU    64
#define DB    128
#define H     128

// weight k-offsets in transposed hi/lo store
#define WO_WU   0
#define WO_WUB  64
#define WO_WBB  192
#define WO_WL1  320
#define WO_WR1  448
#define WO_WL2  576
#define WO_WR2  704
#define WO_WF1A 832
#define WO_WF1B 960
#define WT_TOTK 1088

// ---------------- device scratch ----------------
__device__ int   g_degall[NA];
__device__ int   g_offall[NA];
__device__ int   g_cur[NN];
__device__ int   g_curb[B_N];
__device__ int   g_adj[2 * E_UB];
__device__ int   g_adjb[E_BB];
__device__ int   g_bsums[1024];
__device__ float g_dinv[NN];
__device__ float g_acc[(size_t)NN * H];
__device__ float g_ya[(size_t)NN * H];
__device__ float g_yb[(size_t)NN * H];
__device__ float g_ha[(size_t)B_N * H];
__device__ float g_hb[(size_t)B_N * H];
__device__ float g_agg[(size_t)B_N * H];
__device__ float g_fused[(size_t)B_N * H];
__device__ uint32_t g_wt_hi[WT_TOTK * 64];   // [seg][n][k/2] bf16x2 pairs, W^T layout
__device__ uint32_t g_wt_lo[WT_TOTK * 64];

__device__ __forceinline__ float ftrunc16(float x) {
    return __uint_as_float(__float_as_uint(x) & 0xFFFF0000u);
}
__device__ __forceinline__ uint32_t bf16x2_pack(float lo_elem, float hi_elem) {
    uint32_t r;
    asm("cvt.rn.bf16x2.f32 %0, %1, %2;" : "=r"(r) : "f"(hi_elem), "f"(lo_elem));
    return r;
}

// ---------------- init: zero counters + precompute weight hi/lo panels ----------------
__global__ void k_init(const float* __restrict__ Wu, const float* __restrict__ Wub,
                       const float* __restrict__ Wbb, const float* __restrict__ Wl1,
                       const float* __restrict__ Wr1, const float* __restrict__ Wl2,
                       const float* __restrict__ Wr2, const float* __restrict__ Wf1) {
    int i = blockIdx.x * blockDim.x + threadIdx.x;
    if (i < NA) g_degall[i] = 0;
    if (i < NN) g_cur[i] = 0;
    if (i < B_N) g_curb[i] = 0;
    if (i < WT_TOTK * 64) {
        const int offs[10] = {0, 64, 192, 320, 448, 576, 704, 832, 960, 1088};
        const float* Wp[9] = {Wu, Wub, Wbb, Wl1, Wr1, Wl2, Wr2, Wf1, Wf1 + 128 * 128};
        int e = i * 2;
        int s = 0;
        while (e >= offs[s + 1] * 128) s++;
        int Kw = offs[s + 1] - offs[s];
        int loc = e - offs[s] * 128;
        int n = loc / Kw, k = loc - n * Kw;
        const float* W = Wp[s];
        float a = W[(size_t)k * H + n];
        float b = W[(size_t)(k + 1) * H + n];
        g_wt_hi[i] = __byte_perm(__float_as_uint(a), __float_as_uint(b), 0x7632);
        g_wt_lo[i] = bf16x2_pack(a - ftrunc16(a), b - ftrunc16(b));
    }
}

// ---------------- graph build ----------------
__global__ void k_deg(const int* __restrict__ usrc, const int* __restrict__ udst,
                      const int* __restrict__ bdst) {
    int e = blockIdx.x * blockDim.x + threadIdx.x;
    if (e < E_UB) {
        atomicAdd(&g_degall[usrc[e]], 1);
        atomicAdd(&g_degall[U_N + udst[e]], 1);
    }
    if (e < E_BB) atomicAdd(&g_degall[NN + bdst[e]], 1);
}

__global__ void k_blocksum(const int* __restrict__ in, int n, int* __restrict__ bs) {
    __shared__ int sh[1024];
    int t = threadIdx.x, i = blockIdx.x * 1024 + t;
    sh[t] = (i < n) ? in[i] : 0;
    __syncthreads();
    for (int s = 512; s > 0; s >>= 1) {
        if (t < s) sh[t] += sh[t + s];
        __syncthreads();
    }
    if (t == 0) bs[blockIdx.x] = sh[0];
}

__global__ void k_scan_small(int* bs, int nb) {
    __shared__ int sh[1024];
    int t = threadIdx.x;
    sh[t] = (t < nb) ? bs[t] : 0;
    __syncthreads();
    for (int o = 1; o < 1024; o <<= 1) {
        int v = (t >= o) ? sh[t - o] : 0;
        __syncthreads();
        sh[t] += v;
        __syncthreads();
    }
    if (t < nb) bs[t] = t ? sh[t - 1] : 0;
}

__global__ void k_scan_block(const int* __restrict__ in, int n,
                             const int* __restrict__ bs, int* __restrict__ out) {
    __shared__ int sh[1024];
    int t = threadIdx.x, i = blockIdx.x * 1024 + t;
    int d = (i < n) ? in[i] : 0;
    sh[t] = d;
    __syncthreads();
    for (int o = 1; o < 1024; o <<= 1) {
        int v = (t >= o) ? sh[t - o] : 0;
        __syncthreads();
        sh[t] += v;
        __syncthreads();
    }
    if (i < n) {
        out[i] = (t ? sh[t - 1] : 0) + bs[blockIdx.x];
        if (i < NN) g_dinv[i] = (d > 0) ? rsqrtf((float)d) : 0.0f;
    }
}

// 2 edges per thread: doubled per-warp MLP, half the warps
__global__ void k_fill(const int* __restrict__ usrc, const int* __restrict__ udst,
                       const int* __restrict__ bsrc, const int* __restrict__ bdst) {
    int e0 = (blockIdx.x * blockDim.x + threadIdx.x) * 2;
#pragma unroll
    for (int j = 0; j < 2; j++) {
        int e = e0 + j;
        if (e < E_UB) {
            int u = usrc[e], b = U_N + udst[e];
            int p = atomicAdd(&g_cur[u], 1);
            g_adj[g_offall[u] + p] = b;
            int q = atomicAdd(&g_cur[b], 1);
            g_adj[g_offall[b] + q] = u;
        }
        if (e < E_BB) {
            int d = bdst[e];
            int p = atomicAdd(&g_curb[d], 1);
            g_adjb[g_offall[NN + d] - 2 * E_UB + p] = bsrc[e];
        }
    }
}

// ---------------- bf16 split-3 HMMA GEMM core ----------------
#define GF_RELU   2
#define GF_WRITEY 4
#define GF_FUSE   16

#define MMA_BF16(d, a, b) \
    asm volatile("mma.sync.aligned.m16n8k16.row.col.f32.bf16.bf16.f32 " \
                 "{%0,%1,%2,%3}, {%4,%5,%6,%7}, {%8,%9}, {%0,%1,%2,%3};" \
                 : "+f"((d)[0]), "+f"((d)[1]), "+f"((d)[2]), "+f"((d)[3]) \
                 : "r"((a)[0]), "r"((a)[1]), "r"((a)[2]), "r"((a)[3]), \
                   "r"((b)[0]), "r"((b)[1]))

struct SmemT {
    __nv_bfloat16 Ah[128][36];
    __nv_bfloat16 Al[128][36];
    __nv_bfloat16 Bh[128][34];
    __nv_bfloat16 Bl[128][34];
    float z0s[4][128];
    float z1s[4][128];
};

__device__ __forceinline__ void gemm_body(
    SmemT& sm, int mblk,
    const float* __restrict__ A1, int wo1, int K1, float s1,
    const float* __restrict__ A2, int wo2, int K2,
    const float* __restrict__ bias, float* __restrict__ C, int M, int flags,
    float* __restrict__ Y, const float* __restrict__ dinv,
    const float* __restrict__ Wf2, const float* __restrict__ bf2) {
    const int tid = threadIdx.x;
    const int lane = tid & 31, wid = tid >> 5;
    const int g = lane >> 2, t = lane & 3;
    const int wm = wid >> 2, wn = wid & 3;
    const int m0 = mblk * 128;
    const int np1 = K1 >> 5, np = np1 + (K2 >> 5);

    float acc[4][4][4];
#pragma unroll
    for (int i = 0; i < 4; i++)
#pragma unroll
        for (int j = 0; j < 4; j++) {
            acc[i][j][0] = 0.f; acc[i][j][1] = 0.f;
            acc[i][j][2] = 0.f; acc[i][j][3] = 0.f;
        }

    int arow[4], ac4[4];
#pragma unroll
    for (int i = 0; i < 4; i++) {
        int idx = tid + (i << 8);
        arow[i] = idx >> 3;
        ac4[i] = (idx & 7) << 2;
    }
    const int bn0 = (tid * 2) >> 2, bg0 = (tid * 2) & 3;
    const int bn1 = (tid * 2 + 1) >> 2, bg1 = (tid * 2 + 1) & 3;

    float4 av[4];
    float scs;
    {
        const float* Ap = np1 ? A1 : A2;
        int Ks = np1 ? K1 : K2;
        scs = np1 ? s1 : 1.0f;
#pragma unroll
        for (int i = 0; i < 4; i++) {
            int m = m0 + arow[i];
            av[i] = make_float4(0.f, 0.f, 0.f, 0.f);
            if (m < M) av[i] = *(const float4*)(Ap + (size_t)m * Ks + ac4[i]);
        }
    }

    for (int p = 0; p < np; p++) {
        int wo, Kw, kl;
        if (p < np1) { wo = wo1; Kw = K1; kl = p << 5; }
        else         { wo = wo2; Kw = K2; kl = (p - np1) << 5; }

        const uint32_t* bhp = g_wt_hi + wo * 64;
        const uint32_t* blp = g_wt_lo + wo * 64;
        int bi0 = ((bn0 * Kw + kl) >> 1) + bg0 * 4;
        int bi1 = ((bn1 * Kw + kl) >> 1) + bg1 * 4;
        uint4 BH0 = *(const uint4*)(bhp + bi0);
        uint4 BH1 = *(const uint4*)(bhp + bi1);
        uint4 BL0 = *(const uint4*)(blp + bi0);
        uint4 BL1 = *(const uint4*)(blp + bi1);

#pragma unroll
        for (int i = 0; i < 4; i++) {
            float x0 = scs * av[i].x, x1 = scs * av[i].y;
            float x2 = scs * av[i].z, x3 = scs * av[i].w;
            uint32_t hp0 = __byte_perm(__float_as_uint(x0), __float_as_uint(x1), 0x7632);
            uint32_t hp1 = __byte_perm(__float_as_uint(x2), __float_as_uint(x3), 0x7632);
            uint32_t lp0 = bf16x2_pack(x0 - ftrunc16(x0), x1 - ftrunc16(x1));
            uint32_t lp1 = bf16x2_pack(x2 - ftrunc16(x2), x3 - ftrunc16(x3));
            *(uint32_t*)&sm.Ah[arow[i]][ac4[i]]     = hp0;
            *(uint32_t*)&sm.Ah[arow[i]][ac4[i] + 2] = hp1;
            *(uint32_t*)&sm.Al[arow[i]][ac4[i]]     = lp0;
            *(uint32_t*)&sm.Al[arow[i]][ac4[i] + 2] = lp1;
        }
        *(uint32_t*)&sm.Bh[bn0][bg0 * 8 + 0] = BH0.x;
        *(uint32_t*)&sm.Bh[bn0][bg0 * 8 + 2] = BH0.y;
        *(uint32_t*)&sm.Bh[bn0][bg0 * 8 + 4] = BH0.z;
        *(uint32_t*)&sm.Bh[bn0][bg0 * 8 + 6] = BH0.w;
        *(uint32_t*)&sm.Bh[bn1][bg1 * 8 + 0] = BH1.x;
        *(uint32_t*)&sm.Bh[bn1][bg1 * 8 + 2] = BH1.y;
        *(uint32_t*)&sm.Bh[bn1][bg1 * 8 + 4] = BH1.z;
        *(uint32_t*)&sm.Bh[bn1][bg1 * 8 + 6] = BH1.w;
        *(uint32_t*)&sm.Bl[bn0][bg0 * 8 + 0] = BL0.x;
        *(uint32_t*)&sm.Bl[bn0][bg0 * 8 + 2] = BL0.y;
        *(uint32_t*)&sm.Bl[bn0][bg0 * 8 + 4] = BL0.z;
        *(uint32_t*)&sm.Bl[bn0][bg0 * 8 + 6] = BL0.w;
        *(uint32_t*)&sm.Bl[bn1][bg1 * 8 + 0] = BL1.x;
        *(uint32_t*)&sm.Bl[bn1][bg1 * 8 + 2] = BL1.y;
        *(uint32_t*)&sm.Bl[bn1][bg1 * 8 + 4] = BL1.z;
        *(uint32_t*)&sm.Bl[bn1][bg1 * 8 + 6] = BL1.w;
        __syncthreads();

        float nsc = scs;
        if (p + 1 < np) {
            int q = p + 1;
            const float* Ap; int Ks, kl2;
            if (q < np1) { Ap = A1; Ks = K1; kl2 = q << 5; nsc = s1; }
            else         { Ap = A2; Ks = K2; kl2 = (q - np1) << 5; nsc = 1.0f; }
#pragma unroll
            for (int i = 0; i < 4; i++) {
                int m = m0 + arow[i];
                av[i] = make_float4(0.f, 0.f, 0.f, 0.f);
                if (m < M) av[i] = *(const float4*)(Ap + (size_t)m * Ks + kl2 + ac4[i]);
            }
        }

#pragma unroll
        for (int ks = 0; ks < 2; ks++) {
            const int kk = (ks << 4) + 2 * t;
            uint32_t bh[4][2], bl[4][2];
#pragma unroll
            for (int nf = 0; nf < 4; nf++) {
                int n = (wn << 5) + (nf << 3) + g;
                bh[nf][0] = *(const uint32_t*)&sm.Bh[n][kk];
                bh[nf][1] = *(const uint32_t*)&sm.Bh[n][kk + 8];
                bl[nf][0] = *(const uint32_t*)&sm.Bl[n][kk];
                bl[nf][1] = *(const uint32_t*)&sm.Bl[n][kk + 8];
            }
#pragma unroll
            for (int mf = 0; mf < 4; mf++) {
                int r = (wm << 6) + (mf << 4) + g;
                uint32_t ah[4], al[4];
                ah[0] = *(const uint32_t*)&sm.Ah[r][kk];
                ah[1] = *(const uint32_t*)&sm.Ah[r + 8][kk];
                ah[2] = *(const uint32_t*)&sm.Ah[r][kk + 8];
                ah[3] = *(const uint32_t*)&sm.Ah[r + 8][kk + 8];
                al[0] = *(const uint32_t*)&sm.Al[r][kk];
                al[1] = *(const uint32_t*)&sm.Al[r + 8][kk];
                al[2] = *(const uint32_t*)&sm.Al[r][kk + 8];
                al[3] = *(const uint32_t*)&sm.Al[r + 8][kk + 8];
#pragma unroll
                for (int nf = 0; nf < 4; nf++) {
                    MMA_BF16(acc[mf][nf], ah, bh[nf]);
                    MMA_BF16(acc[mf][nf], ah, bl[nf]);
                    MMA_BF16(acc[mf][nf], al, bh[nf]);
                }
            }
        }
        __syncthreads();
        scs = nsc;
    }

    if (!(flags & GF_FUSE)) {
#pragma unroll
        for (int mf = 0; mf < 4; mf++) {
#pragma unroll
            for (int half = 0; half < 2; half++) {
                int r = m0 + (wm << 6) + (mf << 4) + g + half * 8;
                if (r >= M) continue;
                float dv = (flags & GF_WRITEY) ? dinv[r] : 0.f;
#pragma unroll
                for (int nf = 0; nf < 4; nf++) {
                    int c = (wn << 5) + (nf << 3) + 2 * t;
                    float v0 = acc[mf][nf][half * 2 + 0];
                    float v1 = acc[mf][nf][half * 2 + 1];
                    if (bias) { v0 += __ldg(bias + c); v1 += __ldg(bias + c + 1); }
                    if (flags & GF_RELU) { v0 = fmaxf(v0, 0.f); v1 = fmaxf(v1, 0.f); }
                    *(float2*)(C + (size_t)r * H + c) = make_float2(v0, v1);
                    if (flags & GF_WRITEY)
                        *(float2*)(Y + (size_t)r * H + c) = make_float2(dv * v0, dv * v1);
                }
            }
        }
    } else {
        // fused attention epilogue
#pragma unroll
        for (int mf = 0; mf < 4; mf++) {
#pragma unroll
            for (int half = 0; half < 2; half++) {
                float z0 = 0.f, z1 = 0.f;
#pragma unroll
                for (int nf = 0; nf < 4; nf++) {
                    int c = (wn << 5) + (nf << 3) + 2 * t;
                    float v0 = fmaxf(acc[mf][nf][half * 2 + 0] + __ldg(bias + c), 0.f);
                    float v1 = fmaxf(acc[mf][nf][half * 2 + 1] + __ldg(bias + c + 1), 0.f);
                    const float* w2 = Wf2 + 2 * c;
                    z0 += v0 * __ldg(w2 + 0) + v1 * __ldg(w2 + 2);
                    z1 += v0 * __ldg(w2 + 1) + v1 * __ldg(w2 + 3);
                }
                z0 += __shfl_xor_sync(0xffffffffu, z0, 1);
                z0 += __shfl_xor_sync(0xffffffffu, z0, 2);
                z1 += __shfl_xor_sync(0xffffffffu, z1, 1);
                z1 += __shfl_xor_sync(0xffffffffu, z1, 2);
                if (t == 0) {
                    int rl = (wm << 6) + (mf << 4) + g + half * 8;
                    sm.z0s[wn][rl] = z0;
                    sm.z1s[wn][rl] = z1;
                }
            }
        }
        __syncthreads();
        const float third = 1.0f / 3.0f;
        float b0 = __ldg(bf2), b1 = __ldg(bf2 + 1);
#pragma unroll
        for (int mf = 0; mf < 4; mf++) {
#pragma unroll
            for (int half = 0; half < 2; half++) {
                int rl = (wm << 6) + (mf << 4) + g + half * 8;
                int r = m0 + rl;
                if (r >= M) continue;
                float z0 = sm.z0s[0][rl] + sm.z0s[1][rl] + sm.z0s[2][rl] + sm.z0s[3][rl] + b0;
                float z1 = sm.z1s[0][rl] + sm.z1s[1][rl] + sm.z1s[2][rl] + sm.z1s[3][rl] + b1;
                float mx = fmaxf(z0, z1);
                float e0 = expf(z0 - mx), e1 = expf(z1 - mx);
                float inv = 1.0f / (e0 + e1);
                float a0 = e0 * inv * third, a1 = e1 * inv;
#pragma unroll
                for (int nf = 0; nf < 4; nf++) {
                    int c = (wn << 5) + (nf << 3) + 2 * t;
                    float2 cb = *(const float2*)(g_acc + (size_t)(U_N + r) * H + c);
                    float2 ct = *(const float2*)(g_ha + (size_t)r * H + c);
                    *(float2*)(g_fused + (size_t)r * H + c) =
                        make_float2(a0 * cb.x + a1 * ct.x, a0 * cb.y + a1 * ct.y);
                }
            }
        }
    }
}

#define GU_BLKS 782
#define GB_BLKS 391

__global__ __launch_bounds__(256)
void k_gemm3(const float* __restrict__ user_x, const float* __restrict__ book_x,
             const float* __restrict__ bu, const float* __restrict__ bub,
             const float* __restrict__ bbb) {
    __shared__ SmemT sm;
    int b = blockIdx.x;
    const float* A; const float* bi; float* Cp; float* Yp; const float* dv;
    int wo, K, M, fl, mblk;
    if (b < GU_BLKS) {
        mblk = b; A = user_x; wo = WO_WU; K = DU; M = U_N; bi = bu;
        Cp = g_acc; fl = GF_WRITEY; Yp = g_ya; dv = g_dinv;
    } else if (b < GU_BLKS + GB_BLKS) {
        mblk = b - GU_BLKS; A = book_x; wo = WO_WUB; K = DB; M = B_N; bi = bub;
        Cp = g_acc + (size_t)U_N * H; fl = GF_WRITEY;
        Yp = g_ya + (size_t)U_N * H; dv = g_dinv + U_N;
    } else {
        mblk = b - GU_BLKS - GB_BLKS; A = book_x; wo = WO_WBB; K = DB; M = B_N;
        bi = bbb; Cp = g_ha; fl = 0; Yp = nullptr; dv = nullptr;
    }
    gemm_body(sm, mblk, A, wo, K, 1.0f, nullptr, 0, 0, bi, Cp, M, fl, Yp, dv,
              nullptr, nullptr);
}

__global__ __launch_bounds__(256)
void k_gemm1(const float* __restrict__ A1, int wo1, int K1, float s1,
             const float* __restrict__ A2, int wo2, int K2,
             const float* __restrict__ bias, float* __restrict__ C,
             int M, int flags,
             const float* __restrict__ Wf2, const float* __restrict__ bf2) {
    __shared__ SmemT sm;
    gemm_body(sm, blockIdx.x, A1, wo1, K1, s1, A2, wo2, K2, bias, C, M, flags,
              nullptr, nullptr, Wf2, bf2);
}

// ---- merged SpMV: LightGCN (warps [0,NN)) + SAGE mean-agg (warps [NN,NN+B_N)) ----
__global__ void k_spmv(const float4* __restrict__ yin, float4* __restrict__ yout,
                       int write_yn, const float4* __restrict__ hin) {
    int w = (blockIdx.x * blockDim.x + threadIdx.x) >> 5;
    int lane = threadIdx.x & 31;
    if (w < NN) {
        int start = g_offall[w], d = g_degall[w];
        float4 s = make_float4(0.f, 0.f, 0.f, 0.f);
        int base = 0;
        for (; base + 32 <= d; base += 32) {
            int nb = g_adj[start + base + lane];
#pragma unroll
            for (int j = 0; j < 32; j++) {
                int nbj = __shfl_sync(0xffffffffu, nb, j);
                float4 v = yin[(size_t)nbj * 32 + lane];
                s.x += v.x; s.y += v.y; s.z += v.z; s.w += v.w;
            }
        }
        int rem = d - base;
        if (rem) {
            int nb = (lane < rem) ? g_adj[start + base + lane] : 0;
#pragma unroll 4
            for (int j = 0; j < rem; j++) {
                int nbj = __shfl_sync(0xffffffffu, nb, j);
                float4 v = yin[(size_t)nbj * 32 + lane];
                s.x += v.x; s.y += v.y; s.z += v.z; s.w += v.w;
            }
        }
        float di = g_dinv[w];
        size_t o = (size_t)w * 32 + lane;
        float4 aa = ((float4*)g_acc)[o];
        aa.x += di * s.x; aa.y += di * s.y; aa.z += di * s.z; aa.w += di * s.w;
        ((float4*)g_acc)[o] = aa;
        if (write_yn) {
            float dd = di * di;
            yout[o] = make_float4(dd * s.x, dd * s.y, dd * s.z, dd * s.w);
        }
    } else if (w < NN + B_N) {
        int wb = w - NN;
        int start = g_offall[NN + wb] - 2 * E_UB, d = g_degall[NN + wb];
        float4 s = make_float4(0.f, 0.f, 0.f, 0.f);
        int base = 0;
        for (; base + 32 <= d; base += 32) {
            int nb = g_adjb[start + base + lane];
#pragma unroll
            for (int j = 0; j < 32; j++) {
                int nbj = __shfl_sync(0xffffffffu, nb, j);
                float4 v = hin[(size_t)nbj * 32 + lane];
                s.x += v.x; s.y += v.y; s.z += v.z; s.w += v.w;
            }
        }
        int rem = d - base;
        if (rem) {
            int nb = (lane < rem) ? g_adjb[start + base + lane] : 0;
#pragma unroll 4
            for (int j = 0; j < rem; j++) {
                int nbj = __shfl_sync(0xffffffffu, nb, j);
                float4 v = hin[(size_t)nbj * 32 + lane];
                s.x += v.x; s.y += v.y; s.z += v.z; s.w += v.w;
            }
        }
        float inv = 1.0f / (float)max(d, 1);
        ((float4*)g_agg)[(size_t)wb * 32 + lane] =
            make_float4(inv * s.x, inv * s.y, inv * s.z, inv * s.w);
    }
}

// ---------------- final scoring: quarter-warp (8 lanes) per pair ----------------
__global__ void k_score(const int* __restrict__ pu, const int* __restrict__ pb,
                        float* __restrict__ out) {
    int q = (blockIdx.x * blockDim.x + threadIdx.x) >> 3;
    int l8 = threadIdx.x & 7;
    if (q >= P_N) return;
    int u = pu[q], b = pb[q];
    const float4* ar = (const float4*)g_acc + (size_t)u * 32;
    const float4* fr = (const float4*)g_fused + (size_t)b * 32;
    float s = 0.f;
#pragma unroll
    for (int c = 0; c < 4; c++) {
        float4 a = ar[l8 + c * 8];
        float4 f = fr[l8 + c * 8];
        s += a.x * f.x + a.y * f.y + a.z * f.z + a.w * f.w;
    }
#pragma unroll
    for (int o = 4; o > 0; o >>= 1) s += __shfl_xor_sync(0xffffffffu, s, o);
    if (l8 == 0) out[q] = s * (1.0f / 3.0f);
}

// ---------------- host ----------------
extern "C" void kernel_launch(void* const* d_in, const int* in_sizes, int n_in,
                              void* d_out, int out_size) {
    const float* user_x = (const float*)d_in[0];
    const float* book_x = (const float*)d_in[1];
    const int* ub_src = (const int*)d_in[2];
    const int* ub_dst = (const int*)d_in[3];
    const int* bb_src = (const int*)d_in[4];
    const int* bb_dst = (const int*)d_in[5];
    const int* pred_u = (const int*)d_in[6];
    const int* pred_b = (const int*)d_in[7];
    const float* Wu  = (const float*)d_in[8];
    const float* bu  = (const float*)d_in[9];
    const float* Wub = (const float*)d_in[10];
    const float* bub = (const float*)d_in[11];
    const float* Wbb = (const float*)d_in[12];
    const float* bbb = (const float*)d_in[13];
    const float* Wl1 = (const float*)d_in[14];
    const float* bl1 = (const float*)d_in[15];
    const float* Wr1 = (const float*)d_in[16];
    const float* Wl2 = (const float*)d_in[17];
    const float* bl2 = (const float*)d_in[18];
    const float* Wr2 = (const float*)d_in[19];
    const float* Wf1 = (const float*)d_in[20];
    const float* bf1 = (const float*)d_in[21];
    const float* Wf2 = (const float*)d_in[22];
    const float* bf2 = (const float*)d_in[23];
    float* out = (float*)d_out;

    void *p_acc, *p_ha, *p_hb, *p_agg, *p_deg, *p_off, *p_bs, *p_ya, *p_yb;
    cudaGetSymbolAddress(&p_acc, g_acc);
    cudaGetSymbolAddress(&p_ha, g_ha);
    cudaGetSymbolAddress(&p_hb, g_hb);
    cudaGetSymbolAddress(&p_agg, g_agg);
    cudaGetSymbolAddress(&p_deg, g_degall);
    cudaGetSymbolAddress(&p_off, g_offall);
    cudaGetSymbolAddress(&p_bs, g_bsums);
    cudaGetSymbolAddress(&p_ya, g_ya);
    cudaGetSymbolAddress(&p_yb, g_yb);
    float* acc = (float*)p_acc;
    float* ha = (float*)p_ha;
    float* hb = (float*)p_hb;
    float* agg = (float*)p_agg;
    int* dg = (int*)p_deg;
    int* off = (int*)p_off;
    int* bs = (int*)p_bs;
    float4* ya4 = (float4*)p_ya;
    float4* yb4 = (float4*)p_yb;
    float4* ha4 = (float4*)p_ha;
    float4* hb4 = (float4*)p_hb;

    const int TB = 256;
    const int NB_A = (NA + TB - 1) / TB;
    const int NB_E = (E_UB + TB - 1) / TB;
    const int NB_F = (E_UB / 2 + TB - 1) / TB;   // 2 edges/thread
    const int SCAN_A = (NA + 1023) / 1024;
    const int SPMV_BLKS = ((NN + B_N) * 32 + TB - 1) / TB;

    // init + build prefix
    k_init<<<NB_A, TB>>>(Wu, Wub, Wbb, Wl1, Wr1, Wl2, Wr2, Wf1);
    k_deg<<<NB_E, TB>>>(ub_src, ub_dst, bb_dst);
    k_blocksum<<<SCAN_A, 1024>>>(dg, NA, bs);
    k_scan_small<<<1, 1024>>>(bs, SCAN_A);
    k_scan_block<<<SCAN_A, 1024>>>(dg, NA, bs, off);

    // big projection GEMM
    k_gemm3<<<GU_BLKS + 2 * GB_BLKS, 256>>>(user_x, book_x, bu, bub, bbb);

    // adjacency fill (independent of gemm3; 2 edges/thread)
    k_fill<<<NB_F, TB>>>(ub_src, ub_dst, bb_src, bb_dst);

    // level 0: LightGCN hop1 + SAGE agg(ha)
    k_spmv<<<SPMV_BLKS, TB>>>(ya4, yb4, 1, ha4);

    // SAGE layer 1 (merged L+R)
    k_gemm1<<<GB_BLKS, 256>>>(agg, WO_WL1, H, 1.0f, ha, WO_WR1, H,
                              bl1, hb, B_N, GF_RELU, nullptr, nullptr);

    // level 1: LightGCN hop2 (no yn) + SAGE agg(hb)
    k_spmv<<<SPMV_BLKS, TB>>>(yb4, ya4, 0, hb4);

    // SAGE layer 2
    k_gemm1<<<GB_BLKS, 256>>>(agg, WO_WL2, H, 1.0f, hb, WO_WR2, H,
                              bl2, ha, B_N, GF_RELU, nullptr, nullptr);

    // fusion GEMM with fused attention epilogue
    k_gemm1<<<GB_BLKS, 256>>>(acc + (size_t)U_N * H, WO_WF1A, H, 1.0f / 3.0f,
                              ha, WO_WF1B, H, bf1, nullptr, B_N, GF_FUSE,
                              Wf2, bf2);

    // scoring (quarter-warp per pair)
    k_score<<<(P_N * 8 + TB - 1) / TB, TB>>>(pred_u, pred_b, out);
}

// round 17
// speedup vs baseline: 1.0398x; 1.0124x over previous
#include <cuda_runtime.h>
#include <cuda_bf16.h>
#include <cstdint>
#include <math.h>

// Problem constants
#define U_N   100000
#define B_N   50000
#define NN    150000
#define NA    200000
#define E_UB  800000
#define E_BB  600000
#define P_N   400000
#define DU    64
#define DB    128
#define H     128

// weight k-offsets in transposed hi/lo store
#define WO_WU   0
#define WO_WUB  64
#define WO_WBB  192
#define WO_WL1  320
#define WO_WR1  448
#define WO_WL2  576
#define WO_WR2  704
#define WO_WF1A 832
#define WO_WF1B 960
#define WT_TOTK 1088

// ---------------- device scratch ----------------
__device__ int   g_degall[NA];
__device__ int   g_offall[NA];
__device__ int   g_cur[NN];
__device__ int   g_curb[B_N];
__device__ int   g_adj[2 * E_UB];
__device__ int   g_adjb[E_BB];
__device__ int   g_bsums[1024];
__device__ float g_dinv[NN];
__device__ float g_acc[(size_t)NN * H];
__device__ float g_ya[(size_t)NN * H];
__device__ float g_yb[(size_t)NN * H];
__device__ float g_ha[(size_t)B_N * H];
__device__ float g_hb[(size_t)B_N * H];
__device__ float g_agg[(size_t)B_N * H];
__device__ float g_fused[(size_t)B_N * H];
__device__ uint32_t g_wt_hi[WT_TOTK * 64];   // [seg][n][k/2] bf16x2 pairs, W^T layout
__device__ uint32_t g_wt_lo[WT_TOTK * 64];

__device__ __forceinline__ float ftrunc16(float x) {
    return __uint_as_float(__float_as_uint(x) & 0xFFFF0000u);
}
__device__ __forceinline__ uint32_t bf16x2_pack(float lo_elem, float hi_elem) {
    uint32_t r;
    asm("cvt.rn.bf16x2.f32 %0, %1, %2;" : "=r"(r) : "f"(hi_elem), "f"(lo_elem));
    return r;
}

// ---------------- init: zero counters + precompute weight hi/lo panels ----------------
__global__ void k_init(const float* __restrict__ Wu, const float* __restrict__ Wub,
                       const float* __restrict__ Wbb, const float* __restrict__ Wl1,
                       const float* __restrict__ Wr1, const float* __restrict__ Wl2,
                       const float* __restrict__ Wr2, const float* __restrict__ Wf1) {
    int i = blockIdx.x * blockDim.x + threadIdx.x;
    if (i < NA) g_degall[i] = 0;
    if (i < NN) g_cur[i] = 0;
    if (i < B_N) g_curb[i] = 0;
    if (i < WT_TOTK * 64) {
        const int offs[10] = {0, 64, 192, 320, 448, 576, 704, 832, 960, 1088};
        const float* Wp[9] = {Wu, Wub, Wbb, Wl1, Wr1, Wl2, Wr2, Wf1, Wf1 + 128 * 128};
        int e = i * 2;
        int s = 0;
        while (e >= offs[s + 1] * 128) s++;
        int Kw = offs[s + 1] - offs[s];
        int loc = e - offs[s] * 128;
        int n = loc / Kw, k = loc - n * Kw;
        const float* W = Wp[s];
        float a = W[(size_t)k * H + n];
        float b = W[(size_t)(k + 1) * H + n];
        g_wt_hi[i] = __byte_perm(__float_as_uint(a), __float_as_uint(b), 0x7632);
        g_wt_lo[i] = bf16x2_pack(a - ftrunc16(a), b - ftrunc16(b));
    }
}

// ---------------- graph build ----------------
__global__ void k_deg(const int* __restrict__ usrc, const int* __restrict__ udst,
                      const int* __restrict__ bdst) {
    int e = blockIdx.x * blockDim.x + threadIdx.x;
    if (e < E_UB) {
        atomicAdd(&g_degall[usrc[e]], 1);
        atomicAdd(&g_degall[U_N + udst[e]], 1);
    }
    if (e < E_BB) atomicAdd(&g_degall[NN + bdst[e]], 1);
}

__global__ void k_blocksum(const int* __restrict__ in, int n, int* __restrict__ bs) {
    __shared__ int sh[1024];
    int t = threadIdx.x, i = blockIdx.x * 1024 + t;
    sh[t] = (i < n) ? in[i] : 0;
    __syncthreads();
    for (int s = 512; s > 0; s >>= 1) {
        if (t < s) sh[t] += sh[t + s];
        __syncthreads();
    }
    if (t == 0) bs[blockIdx.x] = sh[0];
}

__global__ void k_scan_small(int* bs, int nb) {
    __shared__ int sh[1024];
    int t = threadIdx.x;
    sh[t] = (t < nb) ? bs[t] : 0;
    __syncthreads();
    for (int o = 1; o < 1024; o <<= 1) {
        int v = (t >= o) ? sh[t - o] : 0;
        __syncthreads();
        sh[t] += v;
        __syncthreads();
    }
    if (t < nb) bs[t] = t ? sh[t - 1] : 0;
}

__global__ void k_scan_block(const int* __restrict__ in, int n,
                             const int* __restrict__ bs, int* __restrict__ out) {
    __shared__ int sh[1024];
    int t = threadIdx.x, i = blockIdx.x * 1024 + t;
    int d = (i < n) ? in[i] : 0;
    sh[t] = d;
    __syncthreads();
    for (int o = 1; o < 1024; o <<= 1) {
        int v = (t >= o) ? sh[t - o] : 0;
        __syncthreads();
        sh[t] += v;
        __syncthreads();
    }
    if (i < n) {
        out[i] = (t ? sh[t - 1] : 0) + bs[blockIdx.x];
        if (i < NN) g_dinv[i] = (d > 0) ? rsqrtf((float)d) : 0.0f;
    }
}

__global__ void k_fill(const int* __restrict__ usrc, const int* __restrict__ udst,
                       const int* __restrict__ bsrc, const int* __restrict__ bdst) {
    int e = blockIdx.x * blockDim.x + threadIdx.x;
    if (e < E_UB) {
        int u = usrc[e], b = U_N + udst[e];
        int p = atomicAdd(&g_cur[u], 1);
        g_adj[g_offall[u] + p] = b;
        int q = atomicAdd(&g_cur[b], 1);
        g_adj[g_offall[b] + q] = u;
    }
    if (e < E_BB) {
        int d = bdst[e];
        int p = atomicAdd(&g_curb[d], 1);
        g_adjb[g_offall[NN + d] - 2 * E_UB + p] = bsrc[e];
    }
}

// ---------------- bf16 split-3 HMMA GEMM core ----------------
#define GF_RELU   2
#define GF_WRITEY 4
#define GF_FUSE   16

#define MMA_BF16(d, a, b) \
    asm volatile("mma.sync.aligned.m16n8k16.row.col.f32.bf16.bf16.f32 " \
                 "{%0,%1,%2,%3}, {%4,%5,%6,%7}, {%8,%9}, {%0,%1,%2,%3};" \
                 : "+f"((d)[0]), "+f"((d)[1]), "+f"((d)[2]), "+f"((d)[3]) \
                 : "r"((a)[0]), "r"((a)[1]), "r"((a)[2]), "r"((a)[3]), \
                   "r"((b)[0]), "r"((b)[1]))

struct SmemT {
    __nv_bfloat16 Ah[128][36];
    __nv_bfloat16 Al[128][36];
    __nv_bfloat16 Bh[128][34];
    __nv_bfloat16 Bl[128][34];
    float z0s[4][128];
    float z1s[4][128];
};

__device__ __forceinline__ void gemm_body(
    SmemT& sm, int mblk,
    const float* __restrict__ A1, int wo1, int K1, float s1,
    const float* __restrict__ A2, int wo2, int K2,
    const float* __restrict__ bias, float* __restrict__ C, int M, int flags,
    float* __restrict__ Y, const float* __restrict__ dinv,
    const float* __restrict__ Wf2, const float* __restrict__ bf2) {
    const int tid = threadIdx.x;
    const int lane = tid & 31, wid = tid >> 5;
    const int g = lane >> 2, t = lane & 3;
    const int wm = wid >> 2, wn = wid & 3;
    const int m0 = mblk * 128;
    const int np1 = K1 >> 5, np = np1 + (K2 >> 5);

    float acc[4][4][4];
#pragma unroll
    for (int i = 0; i < 4; i++)
#pragma unroll
        for (int j = 0; j < 4; j++) {
            acc[i][j][0] = 0.f; acc[i][j][1] = 0.f;
            acc[i][j][2] = 0.f; acc[i][j][3] = 0.f;
        }

    int arow[4], ac4[4];
#pragma unroll
    for (int i = 0; i < 4; i++) {
        int idx = tid + (i << 8);
        arow[i] = idx >> 3;
        ac4[i] = (idx & 7) << 2;
    }
    const int bn0 = (tid * 2) >> 2, bg0 = (tid * 2) & 3;
    const int bn1 = (tid * 2 + 1) >> 2, bg1 = (tid * 2 + 1) & 3;

    float4 av[4];
    float scs;
    {
        const float* Ap = np1 ? A1 : A2;
        int Ks = np1 ? K1 : K2;
        scs = np1 ? s1 : 1.0f;
#pragma unroll
        for (int i = 0; i < 4; i++) {
            int m = m0 + arow[i];
            av[i] = make_float4(0.f, 0.f, 0.f, 0.f);
            if (m < M) av[i] = *(const float4*)(Ap + (size_t)m * Ks + ac4[i]);
        }
    }

    for (int p = 0; p < np; p++) {
        int wo, Kw, kl;
        if (p < np1) { wo = wo1; Kw = K1; kl = p << 5; }
        else         { wo = wo2; Kw = K2; kl = (p - np1) << 5; }

        const uint32_t* bhp = g_wt_hi + wo * 64;
        const uint32_t* blp = g_wt_lo + wo * 64;
        int bi0 = ((bn0 * Kw + kl) >> 1) + bg0 * 4;
        int bi1 = ((bn1 * Kw + kl) >> 1) + bg1 * 4;
        uint4 BH0 = *(const uint4*)(bhp + bi0);
        uint4 BH1 = *(const uint4*)(bhp + bi1);
        uint4 BL0 = *(const uint4*)(blp + bi0);
        uint4 BL1 = *(const uint4*)(blp + bi1);

#pragma unroll
        for (int i = 0; i < 4; i++) {
            float x0 = scs * av[i].x, x1 = scs * av[i].y;
            float x2 = scs * av[i].z, x3 = scs * av[i].w;
            uint32_t hp0 = __byte_perm(__float_as_uint(x0), __float_as_uint(x1), 0x7632);
            uint32_t hp1 = __byte_perm(__float_as_uint(x2), __float_as_uint(x3), 0x7632);
            uint32_t lp0 = bf16x2_pack(x0 - ftrunc16(x0), x1 - ftrunc16(x1));
            uint32_t lp1 = bf16x2_pack(x2 - ftrunc16(x2), x3 - ftrunc16(x3));
            *(uint32_t*)&sm.Ah[arow[i]][ac4[i]]     = hp0;
            *(uint32_t*)&sm.Ah[arow[i]][ac4[i] + 2] = hp1;
            *(uint32_t*)&sm.Al[arow[i]][ac4[i]]     = lp0;
            *(uint32_t*)&sm.Al[arow[i]][ac4[i] + 2] = lp1;
        }
        *(uint32_t*)&sm.Bh[bn0][bg0 * 8 + 0] = BH0.x;
        *(uint32_t*)&sm.Bh[bn0][bg0 * 8 + 2] = BH0.y;
        *(uint32_t*)&sm.Bh[bn0][bg0 * 8 + 4] = BH0.z;
        *(uint32_t*)&sm.Bh[bn0][bg0 * 8 + 6] = BH0.w;
        *(uint32_t*)&sm.Bh[bn1][bg1 * 8 + 0] = BH1.x;
        *(uint32_t*)&sm.Bh[bn1][bg1 * 8 + 2] = BH1.y;
        *(uint32_t*)&sm.Bh[bn1][bg1 * 8 + 4] = BH1.z;
        *(uint32_t*)&sm.Bh[bn1][bg1 * 8 + 6] = BH1.w;
        *(uint32_t*)&sm.Bl[bn0][bg0 * 8 + 0] = BL0.x;
        *(uint32_t*)&sm.Bl[bn0][bg0 * 8 + 2] = BL0.y;
        *(uint32_t*)&sm.Bl[bn0][bg0 * 8 + 4] = BL0.z;
        *(uint32_t*)&sm.Bl[bn0][bg0 * 8 + 6] = BL0.w;
        *(uint32_t*)&sm.Bl[bn1][bg1 * 8 + 0] = BL1.x;
        *(uint32_t*)&sm.Bl[bn1][bg1 * 8 + 2] = BL1.y;
        *(uint32_t*)&sm.Bl[bn1][bg1 * 8 + 4] = BL1.z;
        *(uint32_t*)&sm.Bl[bn1][bg1 * 8 + 6] = BL1.w;
        __syncthreads();

        float nsc = scs;
        if (p + 1 < np) {
            int q = p + 1;
            const float* Ap; int Ks, kl2;
            if (q < np1) { Ap = A1; Ks = K1; kl2 = q << 5; nsc = s1; }
            else         { Ap = A2; Ks = K2; kl2 = (q - np1) << 5; nsc = 1.0f; }
#pragma unroll
            for (int i = 0; i < 4; i++) {
                int m = m0 + arow[i];
                av[i] = make_float4(0.f, 0.f, 0.f, 0.f);
                if (m < M) av[i] = *(const float4*)(Ap + (size_t)m * Ks + kl2 + ac4[i]);
            }
        }

#pragma unroll
        for (int ks = 0; ks < 2; ks++) {
            const int kk = (ks << 4) + 2 * t;
            uint32_t bh[4][2], bl[4][2];
#pragma unroll
            for (int nf = 0; nf < 4; nf++) {
                int n = (wn << 5) + (nf << 3) + g;
                bh[nf][0] = *(const uint32_t*)&sm.Bh[n][kk];
                bh[nf][1] = *(const uint32_t*)&sm.Bh[n][kk + 8];
                bl[nf][0] = *(const uint32_t*)&sm.Bl[n][kk];
                bl[nf][1] = *(const uint32_t*)&sm.Bl[n][kk + 8];
            }
#pragma unroll
            for (int mf = 0; mf < 4; mf++) {
                int r = (wm << 6) + (mf << 4) + g;
                uint32_t ah[4], al[4];
                ah[0] = *(const uint32_t*)&sm.Ah[r][kk];
                ah[1] = *(const uint32_t*)&sm.Ah[r + 8][kk];
                ah[2] = *(const uint32_t*)&sm.Ah[r][kk + 8];
                ah[3] = *(const uint32_t*)&sm.Ah[r + 8][kk + 8];
                al[0] = *(const uint32_t*)&sm.Al[r][kk];
                al[1] = *(const uint32_t*)&sm.Al[r + 8][kk];
                al[2] = *(const uint32_t*)&sm.Al[r][kk + 8];
                al[3] = *(const uint32_t*)&sm.Al[r + 8][kk + 8];
#pragma unroll
                for (int nf = 0; nf < 4; nf++) {
                    MMA_BF16(acc[mf][nf], ah, bh[nf]);
                    MMA_BF16(acc[mf][nf], ah, bl[nf]);
                    MMA_BF16(acc[mf][nf], al, bh[nf]);
                }
            }
        }
        __syncthreads();
        scs = nsc;
    }

    if (!(flags & GF_FUSE)) {
#pragma unroll
        for (int mf = 0; mf < 4; mf++) {
#pragma unroll
            for (int half = 0; half < 2; half++) {
                int r = m0 + (wm << 6) + (mf << 4) + g + half * 8;
                if (r >= M) continue;
                float dv = (flags & GF_WRITEY) ? dinv[r] : 0.f;
#pragma unroll
                for (int nf = 0; nf < 4; nf++) {
                    int c = (wn << 5) + (nf << 3) + 2 * t;
                    float v0 = acc[mf][nf][half * 2 + 0];
                    float v1 = acc[mf][nf][half * 2 + 1];
                    if (bias) { v0 += __ldg(bias + c); v1 += __ldg(bias + c + 1); }
                    if (flags & GF_RELU) { v0 = fmaxf(v0, 0.f); v1 = fmaxf(v1, 0.f); }
                    *(float2*)(C + (size_t)r * H + c) = make_float2(v0, v1);
                    if (flags & GF_WRITEY)
                        *(float2*)(Y + (size_t)r * H + c) = make_float2(dv * v0, dv * v1);
                }
            }
        }
    } else {
        // fused attention epilogue
#pragma unroll
        for (int mf = 0; mf < 4; mf++) {
#pragma unroll
            for (int half = 0; half < 2; half++) {
                float z0 = 0.f, z1 = 0.f;
#pragma unroll
                for (int nf = 0; nf < 4; nf++) {
                    int c = (wn << 5) + (nf << 3) + 2 * t;
                    float v0 = fmaxf(acc[mf][nf][half * 2 + 0] + __ldg(bias + c), 0.f);
                    float v1 = fmaxf(acc[mf][nf][half * 2 + 1] + __ldg(bias + c + 1), 0.f);
                    const float* w2 = Wf2 + 2 * c;
                    z0 += v0 * __ldg(w2 + 0) + v1 * __ldg(w2 + 2);
                    z1 += v0 * __ldg(w2 + 1) + v1 * __ldg(w2 + 3);
                }
                z0 += __shfl_xor_sync(0xffffffffu, z0, 1);
                z0 += __shfl_xor_sync(0xffffffffu, z0, 2);
                z1 += __shfl_xor_sync(0xffffffffu, z1, 1);
                z1 += __shfl_xor_sync(0xffffffffu, z1, 2);
                if (t == 0) {
                    int rl = (wm << 6) + (mf << 4) + g + half * 8;
                    sm.z0s[wn][rl] = z0;
                    sm.z1s[wn][rl] = z1;
                }
            }
        }
        __syncthreads();
        const float third = 1.0f / 3.0f;
        float b0 = __ldg(bf2), b1 = __ldg(bf2 + 1);
#pragma unroll
        for (int mf = 0; mf < 4; mf++) {
#pragma unroll
            for (int half = 0; half < 2; half++) {
                int rl = (wm << 6) + (mf << 4) + g + half * 8;
                int r = m0 + rl;
                if (r >= M) continue;
                float z0 = sm.z0s[0][rl] + sm.z0s[1][rl] + sm.z0s[2][rl] + sm.z0s[3][rl] + b0;
                float z1 = sm.z1s[0][rl] + sm.z1s[1][rl] + sm.z1s[2][rl] + sm.z1s[3][rl] + b1;
                float mx = fmaxf(z0, z1);
                float e0 = expf(z0 - mx), e1 = expf(z1 - mx);
                float inv = 1.0f / (e0 + e1);
                float a0 = e0 * inv * third, a1 = e1 * inv;
#pragma unroll
                for (int nf = 0; nf < 4; nf++) {
                    int c = (wn << 5) + (nf << 3) + 2 * t;
                    float2 cb = *(const float2*)(g_acc + (size_t)(U_N + r) * H + c);
                    float2 ct = *(const float2*)(g_ha + (size_t)r * H + c);
                    *(float2*)(g_fused + (size_t)r * H + c) =
                        make_float2(a0 * cb.x + a1 * ct.x, a0 * cb.y + a1 * ct.y);
                }
            }
        }
    }
}

#define GU_BLKS 782
#define GB_BLKS 391

__global__ __launch_bounds__(256)
void k_gemm3(const float* __restrict__ user_x, const float* __restrict__ book_x,
             const float* __restrict__ bu, const float* __restrict__ bub,
             const float* __restrict__ bbb) {
    __shared__ SmemT sm;
    int b = blockIdx.x;
    const float* A; const float* bi; float* Cp; float* Yp; const float* dv;
    int wo, K, M, fl, mblk;
    if (b < GU_BLKS) {
        mblk = b; A = user_x; wo = WO_WU; K = DU; M = U_N; bi = bu;
        Cp = g_acc; fl = GF_WRITEY; Yp = g_ya; dv = g_dinv;
    } else if (b < GU_BLKS + GB_BLKS) {
        mblk = b - GU_BLKS; A = book_x; wo = WO_WUB; K = DB; M = B_N; bi = bub;
        Cp = g_acc + (size_t)U_N * H; fl = GF_WRITEY;
        Yp = g_ya + (size_t)U_N * H; dv = g_dinv + U_N;
    } else {
        mblk = b - GU_BLKS - GB_BLKS; A = book_x; wo = WO_WBB; K = DB; M = B_N;
        bi = bbb; Cp = g_ha; fl = 0; Yp = nullptr; dv = nullptr;
    }
    gemm_body(sm, mblk, A, wo, K, 1.0f, nullptr, 0, 0, bi, Cp, M, fl, Yp, dv,
              nullptr, nullptr);
}

__global__ __launch_bounds__(256)
void k_gemm1(const float* __restrict__ A1, int wo1, int K1, float s1,
             const float* __restrict__ A2, int wo2, int K2,
             const float* __restrict__ bias, float* __restrict__ C,
             int M, int flags,
             const float* __restrict__ Wf2, const float* __restrict__ bf2) {
    __shared__ SmemT sm;
    gemm_body(sm, blockIdx.x, A1, wo1, K1, s1, A2, wo2, K2, bias, C, M, flags,
              nullptr, nullptr, Wf2, bf2);
}

// ---- merged SpMV: LightGCN (warps [0,NN)) + SAGE mean-agg (warps [NN,NN+B_N)) ----
__global__ void k_spmv(const float4* __restrict__ yin, float4* __restrict__ yout,
                       int write_yn, const float4* __restrict__ hin) {
    int w = (blockIdx.x * blockDim.x + threadIdx.x) >> 5;
    int lane = threadIdx.x & 31;
    if (w < NN) {
        int start = g_offall[w], d = g_degall[w];
        float4 s = make_float4(0.f, 0.f, 0.f, 0.f);
        int base = 0;
        for (; base + 32 <= d; base += 32) {
            int nb = g_adj[start + base + lane];
#pragma unroll
            for (int j = 0; j < 32; j++) {
                int nbj = __shfl_sync(0xffffffffu, nb, j);
                float4 v = yin[(size_t)nbj * 32 + lane];
                s.x += v.x; s.y += v.y; s.z += v.z; s.w += v.w;
            }
        }
        int rem = d - base;
        if (rem) {
            int nb = (lane < rem) ? g_adj[start + base + lane] : 0;
#pragma unroll 4
            for (int j = 0; j < rem; j++) {
                int nbj = __shfl_sync(0xffffffffu, nb, j);
                float4 v = yin[(size_t)nbj * 32 + lane];
                s.x += v.x; s.y += v.y; s.z += v.z; s.w += v.w;
            }
        }
        float di = g_dinv[w];
        size_t o = (size_t)w * 32 + lane;
        float4 aa = ((float4*)g_acc)[o];
        aa.x += di * s.x; aa.y += di * s.y; aa.z += di * s.z; aa.w += di * s.w;
        ((float4*)g_acc)[o] = aa;
        if (write_yn) {
            float dd = di * di;
            yout[o] = make_float4(dd * s.x, dd * s.y, dd * s.z, dd * s.w);
        }
    } else if (w < NN + B_N) {
        int wb = w - NN;
        int start = g_offall[NN + wb] - 2 * E_UB, d = g_degall[NN + wb];
        float4 s = make_float4(0.f, 0.f, 0.f, 0.f);
        int base = 0;
        for (; base + 32 <= d; base += 32) {
            int nb = g_adjb[start + base + lane];
#pragma unroll
            for (int j = 0; j < 32; j++) {
                int nbj = __shfl_sync(0xffffffffu, nb, j);
                float4 v = hin[(size_t)nbj * 32 + lane];
                s.x += v.x; s.y += v.y; s.z += v.z; s.w += v.w;
            }
        }
        int rem = d - base;
        if (rem) {
            int nb = (lane < rem) ? g_adjb[start + base + lane] : 0;
#pragma unroll 4
            for (int j = 0; j < rem; j++) {
                int nbj = __shfl_sync(0xffffffffu, nb, j);
                float4 v = hin[(size_t)nbj * 32 + lane];
                s.x += v.x; s.y += v.y; s.z += v.z; s.w += v.w;
            }
        }
        float inv = 1.0f / (float)max(d, 1);
        ((float4*)g_agg)[(size_t)wb * 32 + lane] =
            make_float4(inv * s.x, inv * s.y, inv * s.z, inv * s.w);
    }
}

// ---------------- final scoring: quarter-warp (8 lanes) per pair ----------------
__global__ void k_score(const int* __restrict__ pu, const int* __restrict__ pb,
                        float* __restrict__ out) {
    int q = (blockIdx.x * blockDim.x + threadIdx.x) >> 3;
    int l8 = threadIdx.x & 7;
    if (q >= P_N) return;
    int u = pu[q], b = pb[q];
    const float4* ar = (const float4*)g_acc + (size_t)u * 32;
    const float4* fr = (const float4*)g_fused + (size_t)b * 32;
    float s = 0.f;
#pragma unroll
    for (int c = 0; c < 4; c++) {
        float4 a = ar[l8 + c * 8];
        float4 f = fr[l8 + c * 8];
        s += a.x * f.x + a.y * f.y + a.z * f.z + a.w * f.w;
    }
#pragma unroll
    for (int o = 4; o > 0; o >>= 1) s += __shfl_xor_sync(0xffffffffu, s, o);
    if (l8 == 0) out[q] = s * (1.0f / 3.0f);
}

// ---------------- host ----------------
extern "C" void kernel_launch(void* const* d_in, const int* in_sizes, int n_in,
                              void* d_out, int out_size) {
    const float* user_x = (const float*)d_in[0];
    const float* book_x = (const float*)d_in[1];
    const int* ub_src = (const int*)d_in[2];
    const int* ub_dst = (const int*)d_in[3];
    const int* bb_src = (const int*)d_in[4];
    const int* bb_dst = (const int*)d_in[5];
    const int* pred_u = (const int*)d_in[6];
    const int* pred_b = (const int*)d_in[7];
    const float* Wu  = (const float*)d_in[8];
    const float* bu  = (const float*)d_in[9];
    const float* Wub = (const float*)d_in[10];
    const float* bub = (const float*)d_in[11];
    const float* Wbb = (const float*)d_in[12];
    const float* bbb = (const float*)d_in[13];
    const float* Wl1 = (const float*)d_in[14];
    const float* bl1 = (const float*)d_in[15];
    const float* Wr1 = (const float*)d_in[16];
    const float* Wl2 = (const float*)d_in[17];
    const float* bl2 = (const float*)d_in[18];
    const float* Wr2 = (const float*)d_in[19];
    const float* Wf1 = (const float*)d_in[20];
    const float* bf1 = (const float*)d_in[21];
    const float* Wf2 = (const float*)d_in[22];
    const float* bf2 = (const float*)d_in[23];
    float* out = (float*)d_out;

    void *p_acc, *p_ha, *p_hb, *p_agg, *p_deg, *p_off, *p_bs, *p_ya, *p_yb;
    cudaGetSymbolAddress(&p_acc, g_acc);
    cudaGetSymbolAddress(&p_ha, g_ha);
    cudaGetSymbolAddress(&p_hb, g_hb);
    cudaGetSymbolAddress(&p_agg, g_agg);
    cudaGetSymbolAddress(&p_deg, g_degall);
    cudaGetSymbolAddress(&p_off, g_offall);
    cudaGetSymbolAddress(&p_bs, g_bsums);
    cudaGetSymbolAddress(&p_ya, g_ya);
    cudaGetSymbolAddress(&p_yb, g_yb);
    float* acc = (float*)p_acc;
    float* ha = (float*)p_ha;
    float* hb = (float*)p_hb;
    float* agg = (float*)p_agg;
    int* dg = (int*)p_deg;
    int* off = (int*)p_off;
    int* bs = (int*)p_bs;
    float4* ya4 = (float4*)p_ya;
    float4* yb4 = (float4*)p_yb;
    float4* ha4 = (float4*)p_ha;
    float4* hb4 = (float4*)p_hb;

    const int TB = 256;
    const int NB_A = (NA + TB - 1) / TB;
    const int NB_E = (E_UB + TB - 1) / TB;
    const int SCAN_A = (NA + 1023) / 1024;
    const int SPMV_BLKS = ((NN + B_N) * 32 + TB - 1) / TB;

    // init + build prefix
    k_init<<<NB_A, TB>>>(Wu, Wub, Wbb, Wl1, Wr1, Wl2, Wr2, Wf1);
    k_deg<<<NB_E, TB>>>(ub_src, ub_dst, bb_dst);
    k_blocksum<<<SCAN_A, 1024>>>(dg, NA, bs);
    k_scan_small<<<1, 1024>>>(bs, SCAN_A);
    k_scan_block<<<SCAN_A, 1024>>>(dg, NA, bs, off);

    // big projection GEMM
    k_gemm3<<<GU_BLKS + 2 * GB_BLKS, 256>>>(user_x, book_x, bu, bub, bbb);

    // adjacency fill (independent of gemm3)
    k_fill<<<NB_E, TB>>>(ub_src, ub_dst, bb_src, bb_dst);

    // level 0: LightGCN hop1 + SAGE agg(ha)
    k_spmv<<<SPMV_BLKS, TB>>>(ya4, yb4, 1, ha4);

    // SAGE layer 1 (merged L+R)
    k_gemm1<<<GB_BLKS, 256>>>(agg, WO_WL1, H, 1.0f, ha, WO_WR1, H,
                              bl1, hb, B_N, GF_RELU, nullptr, nullptr);

    // level 1: LightGCN hop2 (no yn) + SAGE agg(hb)
    k_spmv<<<SPMV_BLKS, TB>>>(yb4, ya4, 0, hb4);

    // SAGE layer 2
    k_gemm1<<<GB_BLKS, 256>>>(agg, WO_WL2, H, 1.0f, hb, WO_WR2, H,
                              bl2, ha, B_N, GF_RELU, nullptr, nullptr);

    // fusion GEMM with fused attention epilogue
    k_gemm1<<<GB_BLKS, 256>>>(acc + (size_t)U_N * H, WO_WF1A, H, 1.0f / 3.0f,
                              ha, WO_WF1B, H, bf1, nullptr, B_N, GF_FUSE,
                              Wf2, bf2);

    // scoring (quarter-warp per pair)
    k_score<<<(P_N * 8 + TB - 1) / TB, TB>>>(pred_u, pred_b, out);
}